// round 14
// baseline (speedup 1.0000x reference)
#include <cuda_runtime.h>
#include <math.h>

#define HW     16384
#define IMG    128
#define TS     8
#define RAD    5
#define KW     11
#define HALO   18
#define NNB    121
#define SSTR   124
#define KSTR   325
#define SCALE  0.11785113019775793f  // 1/sqrt(72)

typedef unsigned long long ull;

__device__ float g_scratch[HW * 72 * 8];

__device__ __forceinline__ float gelu_exact(float x) {
    return 0.5f * x * (1.0f + erff(x * 0.70710678118654752f));
}
__device__ __forceinline__ unsigned bf2(float hi, float lo) {
    unsigned r;
    asm("cvt.rn.bf16x2.f32 %0, %1, %2;" : "=r"(r) : "f"(hi), "f"(lo));
    return r;
}
__device__ __forceinline__ float bf_lo(unsigned u) { return __uint_as_float(u << 16); }
__device__ __forceinline__ float bf_hi(unsigned u) { return __uint_as_float(u & 0xffff0000u); }
// tf32 round: b32 destination per PTX spec; bits are a valid fp32 value.
__device__ __forceinline__ float tf32r(float x) {
    unsigned u;
    asm("cvt.rna.tf32.f32 %0, %1;" : "=r"(u) : "f"(x));
    return __uint_as_float(u);
}

#define MMA_TF32(c0,c1,c2,c3,a0,a1,a2,a3,b0,b1) \
    asm("mma.sync.aligned.m16n8k8.row.col.f32.tf32.tf32.f32 " \
        "{%0,%1,%2,%3},{%4,%5,%6,%7},{%8,%9},{%0,%1,%2,%3};" \
        : "+f"(c0), "+f"(c1), "+f"(c2), "+f"(c3) \
        : "r"(a0), "r"(a1), "r"(a2), "r"(a3), "r"(b0), "r"(b1))

// ---------------------------------------------------------------------------
// Tensor-core GEMM: Y[64px,72] = X[64px,72] @ W[72,72] + b  (3xTF32, ~fp32)
// 128 threads = 4 warps; warp = one 16-row M-tile; 9 N-tiles; k in 9 steps.
// ---------------------------------------------------------------------------
__device__ __forceinline__ void tcproj_body(const float* __restrict__ X,
                                            const float* __restrict__ W,
                                            const float* __restrict__ B,
                                            float* __restrict__ Y,
                                            int blk, float* sm) {
    float* Xh = sm;                   // 64*76
    float* Xl = Xh + 64 * 76;         // 64*76
    float* Wh = Xl + 64 * 76;         // 72*72
    float* Wl = Wh + 72 * 72;         // 72*72
    float* bs = Wl + 72 * 72;         // 72
    const int tid = threadIdx.x;
    const int pix0 = blk * 64;

    for (int i = tid; i < 64 * 18; i += 128) {
        int p = i / 18, c4 = i - p * 18;
        float4 v = ((const float4*)(X + pix0 * 72))[i];
        float4 h, l;
        h.x = tf32r(v.x); l.x = tf32r(v.x - h.x);
        h.y = tf32r(v.y); l.y = tf32r(v.y - h.y);
        h.z = tf32r(v.z); l.z = tf32r(v.z - h.z);
        h.w = tf32r(v.w); l.w = tf32r(v.w - h.w);
        *(float4*)&Xh[p * 76 + c4 * 4] = h;
        *(float4*)&Xl[p * 76 + c4 * 4] = l;
    }
    for (int i = tid; i < 72 * 18; i += 128) {
        float4 v = ((const float4*)W)[i];
        float4 h, l;
        h.x = tf32r(v.x); l.x = tf32r(v.x - h.x);
        h.y = tf32r(v.y); l.y = tf32r(v.y - h.y);
        h.z = tf32r(v.z); l.z = tf32r(v.z - h.z);
        h.w = tf32r(v.w); l.w = tf32r(v.w - h.w);
        ((float4*)Wh)[i] = h;
        ((float4*)Wl)[i] = l;
    }
    if (tid < 72) bs[tid] = B[tid];
    __syncthreads();

    const int warp = tid >> 5, lane = tid & 31;
    const int g = lane >> 2, t = lane & 3;
    const int m0 = warp * 16;

    float c[9][4];
#pragma unroll
    for (int nt = 0; nt < 9; nt++)
#pragma unroll
        for (int j = 0; j < 4; j++) c[nt][j] = 0.0f;

    for (int k0 = 0; k0 < 72; k0 += 8) {
        const int r0 = (m0 + g) * 76 + k0 + t;
        const int r8 = (m0 + g + 8) * 76 + k0 + t;
        unsigned ah0 = __float_as_uint(Xh[r0]);
        unsigned ah1 = __float_as_uint(Xh[r8]);
        unsigned ah2 = __float_as_uint(Xh[r0 + 4]);
        unsigned ah3 = __float_as_uint(Xh[r8 + 4]);
        unsigned al0 = __float_as_uint(Xl[r0]);
        unsigned al1 = __float_as_uint(Xl[r8]);
        unsigned al2 = __float_as_uint(Xl[r0 + 4]);
        unsigned al3 = __float_as_uint(Xl[r8 + 4]);
        const int wr0 = (k0 + t) * 72 + g;
        const int wr4 = (k0 + t + 4) * 72 + g;
#pragma unroll
        for (int nt = 0; nt < 9; nt++) {
            unsigned bh0 = __float_as_uint(Wh[wr0 + nt * 8]);
            unsigned bh1 = __float_as_uint(Wh[wr4 + nt * 8]);
            unsigned bl0 = __float_as_uint(Wl[wr0 + nt * 8]);
            unsigned bl1 = __float_as_uint(Wl[wr4 + nt * 8]);
            MMA_TF32(c[nt][0], c[nt][1], c[nt][2], c[nt][3],
                     ah0, ah1, ah2, ah3, bh0, bh1);
            MMA_TF32(c[nt][0], c[nt][1], c[nt][2], c[nt][3],
                     al0, al1, al2, al3, bh0, bh1);
            MMA_TF32(c[nt][0], c[nt][1], c[nt][2], c[nt][3],
                     ah0, ah1, ah2, ah3, bl0, bl1);
        }
    }

#pragma unroll
    for (int nt = 0; nt < 9; nt++) {
        int n = nt * 8 + 2 * t;
        int row0 = pix0 + m0 + g;
        float b0 = bs[n], b1 = bs[n + 1];
        Y[row0 * 72 + n]           = c[nt][0] + b0;
        Y[row0 * 72 + n + 1]       = c[nt][1] + b1;
        Y[(row0 + 8) * 72 + n]     = c[nt][2] + b0;
        Y[(row0 + 8) * 72 + n + 1] = c[nt][3] + b1;
    }
}

#define TCSMEM ((64 * 76 * 2 + 72 * 72 * 2 + 72) * 4)

__global__ __launch_bounds__(128) void tc_quad_kernel(
        const float* __restrict__ X0, const float* __restrict__ W0, const float* __restrict__ B0, float* __restrict__ Y0,
        const float* __restrict__ X1, const float* __restrict__ W1, const float* __restrict__ B1, float* __restrict__ Y1,
        const float* __restrict__ X2, const float* __restrict__ W2, const float* __restrict__ B2, float* __restrict__ Y2,
        const float* __restrict__ X3, const float* __restrict__ W3, const float* __restrict__ B3, float* __restrict__ Y3) {
    extern __shared__ float tcs[];
    int gi = blockIdx.x >> 8, blk = blockIdx.x & 255;
    const float *X, *W, *B;
    float* Y;
    if (gi == 0)      { X = X0; W = W0; B = B0; Y = Y0; }
    else if (gi == 1) { X = X1; W = W1; B = B1; Y = Y1; }
    else if (gi == 2) { X = X2; W = W2; B = B2; Y = Y2; }
    else              { X = X3; W = W3; B = B3; Y = Y3; }
    tcproj_body(X, W, B, Y, blk, tcs);
}

__global__ __launch_bounds__(128) void tc_pair_kernel(
        const float* __restrict__ X0, const float* __restrict__ W0, const float* __restrict__ B0, float* __restrict__ Y0,
        const float* __restrict__ X1, const float* __restrict__ W1, const float* __restrict__ B1, float* __restrict__ Y1) {
    extern __shared__ float tcs[];
    int gi = blockIdx.x >> 8, blk = blockIdx.x & 255;
    const float *X, *W, *B;
    float* Y;
    if (gi == 0) { X = X0; W = W0; B = B0; Y = Y0; }
    else         { X = X1; W = W1; B = B1; Y = Y1; }
    tcproj_body(X, W, B, Y, blk, tcs);
}

// ---------------------------------------------------------------------------
// MLP (gelu) with fused concat (R7 exact)
// ---------------------------------------------------------------------------
template <int TAIL>
__device__ __forceinline__ void mlp_body(const float* __restrict__ g0,
                                         const float* __restrict__ gt,
                                         const float* __restrict__ tail,
                                         const float* __restrict__ W,
                                         const float* __restrict__ B,
                                         float* __restrict__ Y,
                                         int blk, char* smraw) {
    constexpr int DIN = 64 + TAIL;
    float* Xs = (float*)smraw;        // 64*DIN
    float* Ws = Xs + 64 * DIN;        // DIN*72
    float* bs = Ws + DIN * 72;        // 72
    const int tid = threadIdx.x;
    const int pix0 = blk * 64;

    for (int i = tid; i < 64 * 64; i += 288) {
        int p = i >> 6, c = i & 63;
        Xs[p * DIN + c] = g0[(pix0 + p) * 64 + c] + gt[(pix0 + p) * 64 + c];
    }
    for (int i = tid; i < 64 * TAIL; i += 288) {
        int p = i / TAIL, c = i - p * TAIL;
        Xs[p * DIN + 64 + c] = tail[(pix0 + p) * TAIL + c];
    }
    for (int i = tid; i < DIN * 18; i += 288)
        ((float4*)Ws)[i] = ((const float4*)W)[i];
    if (tid < 72) bs[tid] = B[tid];
    __syncthreads();

    const int og = tid % 18, pg = tid / 18;
    const int ob = og * 4, xb = pg * 4;

    float acc[4][4];
#pragma unroll
    for (int i = 0; i < 4; i++)
#pragma unroll
        for (int j = 0; j < 4; j++) acc[i][j] = 0.0f;

    for (int k = 0; k < DIN; k++) {
        float x0 = Xs[(xb + 0) * DIN + k];
        float x1 = Xs[(xb + 1) * DIN + k];
        float x2 = Xs[(xb + 2) * DIN + k];
        float x3 = Xs[(xb + 3) * DIN + k];
        float4 w = *(const float4*)&Ws[k * 72 + ob];
        acc[0][0] += x0 * w.x; acc[0][1] += x0 * w.y; acc[0][2] += x0 * w.z; acc[0][3] += x0 * w.w;
        acc[1][0] += x1 * w.x; acc[1][1] += x1 * w.y; acc[1][2] += x1 * w.z; acc[1][3] += x1 * w.w;
        acc[2][0] += x2 * w.x; acc[2][1] += x2 * w.y; acc[2][2] += x2 * w.z; acc[2][3] += x2 * w.w;
        acc[3][0] += x3 * w.x; acc[3][1] += x3 * w.y; acc[3][2] += x3 * w.z; acc[3][3] += x3 * w.w;
    }
#pragma unroll
    for (int i = 0; i < 4; i++) {
        float4 r;
        r.x = gelu_exact(acc[i][0] + bs[ob + 0]);
        r.y = gelu_exact(acc[i][1] + bs[ob + 1]);
        r.z = gelu_exact(acc[i][2] + bs[ob + 2]);
        r.w = gelu_exact(acc[i][3] + bs[ob + 3]);
        *(float4*)&Y[(pix0 + xb + i) * 72 + ob] = r;
    }
}

__global__ __launch_bounds__(288) void mlp_pair_kernel(const float* __restrict__ g0,
                                                       const float* __restrict__ gt,
                                                       const float* __restrict__ pi,
                                                       const float* __restrict__ f,
                                                       const float* __restrict__ W1,
                                                       const float* __restrict__ B1,
                                                       const float* __restrict__ W2,
                                                       const float* __restrict__ B2,
                                                       float* __restrict__ Yq,
                                                       float* __restrict__ Ykv) {
    __shared__ char smraw[(64 * 72 + 72 * 72 + 72) * 4];
    if (blockIdx.x < 256) mlp_body<8>(g0, gt, pi, W1, B1, Yq,  blockIdx.x, smraw);
    else                  mlp_body<3>(g0, gt, f,  W2, B2, Ykv, blockIdx.x - 256, smraw);
}

// ---------------------------------------------------------------------------
// Attention (R7 exact, frozen): 8x8 tile, 512 threads.
// ---------------------------------------------------------------------------
__global__ __launch_bounds__(512) void attn_kernel(const float* __restrict__ Q,
                                                   const float* __restrict__ Kp,
                                                   const float* __restrict__ Vp,
                                                   float* __restrict__ O) {
    extern __shared__ char smraw[];
    unsigned* Ksh = (unsigned*)smraw;            // 36 * KSTR  (bf16x2 per entry)
    ull*      Vsh = (ull*)(Ksh + 36 * KSTR);     // 324 * 18   (bf16x4 per entry)
    float*    S   = (float*)(Vsh + 324 * 18);    // 64 * SSTR
    float*    red = S + 64 * SSTR;               // 64

    const int tid = threadIdx.x;
    const int tx = blockIdx.x, ty = blockIdx.y;
    const int ox = tx * TS - RAD, oy = ty * TS - RAD;

    for (int i = tid; i < HALO * HALO * 18; i += 512) {
        int cell = i / 18, j = i - cell * 18;
        int hy = cell / HALO, hx = cell - hy * HALO;
        int gy = oy + hy, gx = ox + hx;
        float4 kv = make_float4(0.f, 0.f, 0.f, 0.f);
        float4 vv = kv;
        if ((unsigned)gy < IMG && (unsigned)gx < IMG) {
            int base = (gy * IMG + gx) * 18;
            kv = __ldg((const float4*)Kp + base + j);
            vv = __ldg((const float4*)Vp + base + j);
        }
        Ksh[(2 * j + 0) * KSTR + cell] = bf2(kv.y, kv.x);
        Ksh[(2 * j + 1) * KSTR + cell] = bf2(kv.w, kv.z);
        unsigned v01 = bf2(vv.y, vv.x);
        unsigned v23 = bf2(vv.w, vv.z);
        Vsh[cell * 18 + j] = ((ull)v23 << 32) | (ull)v01;
    }
    __syncthreads();

    const int p = tid >> 3, sub = tid & 7;
    const int py = p >> 3, px = p & 7;
    const int gy = ty * TS + py, gx = tx * TS + px;

    // ---- phase A: scores ----
    {
        float q[72];
        const float4* qr = (const float4*)(Q + (gy * IMG + gx) * 72);
#pragma unroll
        for (int jj = 0; jj < 18; jj++) {
            float4 t = __ldg(qr + jj);
            q[4 * jj + 0] = t.x; q[4 * jj + 1] = t.y;
            q[4 * jj + 2] = t.z; q[4 * jj + 3] = t.w;
        }
        for (int n = sub; n < NNB; n += 8) {
            int qy = n / 11;
            int qx = n - qy * 11;
            int ny = gy + qy - RAD, nx = gx + qx - RAD;
            float s = -INFINITY;
            if ((unsigned)ny < IMG && (unsigned)nx < IMG) {
                const unsigned* kc = Ksh + (py + qy) * HALO + (px + qx);
                float a0 = 0.f, a1 = 0.f, a2 = 0.f, a3 = 0.f;
#pragma unroll
                for (int j2 = 0; j2 < 36; j2 += 2) {
                    unsigned u0 = kc[(j2 + 0) * KSTR];
                    unsigned u1 = kc[(j2 + 1) * KSTR];
                    a0 = fmaf(q[2 * j2 + 0], bf_lo(u0), a0);
                    a1 = fmaf(q[2 * j2 + 1], bf_hi(u0), a1);
                    a2 = fmaf(q[2 * j2 + 2], bf_lo(u1), a2);
                    a3 = fmaf(q[2 * j2 + 3], bf_hi(u1), a3);
                }
                s = (a0 + a1 + a2 + a3) * SCALE;
            }
            S[p * SSTR + n] = s;
        }
    }
    __syncwarp();

    // ---- softmax: 8-lane cooperative ----
    {
        float* row = S + p * SSTR;
        float m = -INFINITY;
        for (int n = sub; n < NNB; n += 8) m = fmaxf(m, row[n]);
        m = fmaxf(m, __shfl_xor_sync(0xffffffffu, m, 1));
        m = fmaxf(m, __shfl_xor_sync(0xffffffffu, m, 2));
        m = fmaxf(m, __shfl_xor_sync(0xffffffffu, m, 4));
        float sum = 0.f;
        for (int n = sub; n < NNB; n += 8) {
            float e = __expf(row[n] - m);
            row[n] = e;
            sum += e;
        }
        sum += __shfl_xor_sync(0xffffffffu, sum, 1);
        sum += __shfl_xor_sync(0xffffffffu, sum, 2);
        sum += __shfl_xor_sync(0xffffffffu, sum, 4);
        if (sub == 0) red[p] = 1.0f / sum;
    }
    __syncthreads();

    // ---- phase B: attn @ V ----
    for (int u = tid; u < 64 * 18; u += 512) {
        int pp = u / 18, j = u - pp * 18;
        int ppy = pp >> 3, ppx = pp & 7;
        const float* arow = S + pp * SSTR;
        float c0 = 0.f, c1 = 0.f, c2 = 0.f, c3 = 0.f;
#pragma unroll 1
        for (int dy = 0; dy < KW; dy++) {
            const ull* vb = Vsh + (((ppy + dy) * HALO) + ppx) * 18 + j;
            const float* ar = arow + dy * KW;
#pragma unroll
            for (int dx = 0; dx < KW; dx++) {
                float a = ar[dx];
                ull v = vb[dx * 18];
                unsigned u0 = (unsigned)v;
                unsigned u1 = (unsigned)(v >> 32);
                c0 = fmaf(a, bf_lo(u0), c0);
                c1 = fmaf(a, bf_hi(u0), c1);
                c2 = fmaf(a, bf_lo(u1), c2);
                c3 = fmaf(a, bf_hi(u1), c3);
            }
        }
        float r = red[pp];
        float4 res = make_float4(c0 * r, c1 * r, c2 * r, c3 * r);
        int ogy = ty * TS + ppy, ogx = tx * TS + ppx;
        ((float4*)O)[(ogy * IMG + ogx) * 18 + j] = res;
    }
}

// ---------------------------------------------------------------------------
// head (blocks 0..63) + split (blocks 64..)
// ---------------------------------------------------------------------------
__global__ __launch_bounds__(256) void head_split_kernel(const float* __restrict__ gp,
                                                         const float* __restrict__ WG,
                                                         const float* __restrict__ BG,
                                                         const float* __restrict__ WP,
                                                         const float* __restrict__ BP,
                                                         float* __restrict__ out) {
    const int tid = threadIdx.x;
    if (blockIdx.x >= 64) {
        int i = (blockIdx.x - 64) * 256 + tid;
        if (i < HW * 72) {
            int pix = i / 72, c = i - pix * 72;
            float v = gp[i];
            if (c < 64) out[HW * 10 + pix * 64 + c] = v;
            else        out[HW * 74 + pix * 8 + (c - 64)] = v;
        }
        return;
    }
    __shared__ float wg[64 * 7];
    __shared__ float bg[7];
    __shared__ float wp[24];
    __shared__ float bp[3];
    for (int i = tid; i < 448; i += 256) wg[i] = WG[i];
    if (tid < 7)  bg[tid] = BG[tid];
    if (tid < 24) wp[tid] = WP[tid];
    if (tid < 3)  bp[tid] = BP[tid];
    __syncthreads();

    int pix = blockIdx.x * 256 + tid;
    const float* row = gp + pix * 72;

    float gr[7];
#pragma unroll
    for (int j = 0; j < 7; j++) gr[j] = bg[j];
    for (int c = 0; c < 64; c++) {
        float x = row[c];
#pragma unroll
        for (int j = 0; j < 7; j++) gr[j] += x * wg[c * 7 + j];
    }
    float go[7];
#pragma unroll
    for (int j = 0; j < 4; j++) go[j] = 1.0f / (1.0f + __expf(-gr[j]));
    {
        float m = fmaxf(gr[4], fmaxf(gr[5], gr[6]));
        float e0 = __expf(gr[4] - m), e1 = __expf(gr[5] - m), e2 = __expf(gr[6] - m);
        float rs = 1.0f / (e0 + e1 + e2);
        go[4] = e0 * rs; go[5] = e1 * rs; go[6] = e2 * rs;
    }
#pragma unroll
    for (int j = 0; j < 7; j++) out[pix * 7 + j] = go[j];

    float pr[3];
#pragma unroll
    for (int j = 0; j < 3; j++) pr[j] = bp[j];
    for (int c = 0; c < 8; c++) {
        float x = row[64 + c];
#pragma unroll
        for (int j = 0; j < 3; j++) pr[j] += x * wp[c * 3 + j];
    }
    {
        float m = fmaxf(pr[0], fmaxf(pr[1], pr[2]));
        float e0 = __expf(pr[0] - m), e1 = __expf(pr[1] - m), e2 = __expf(pr[2] - m);
        float rs = 1.0f / (e0 + e1 + e2);
        out[HW * 7 + pix * 3 + 0] = e0 * rs;
        out[HW * 7 + pix * 3 + 1] = e1 * rs;
        out[HW * 7 + pix * 3 + 2] = e2 * rs;
    }
}

// ---------------------------------------------------------------------------
extern "C" void kernel_launch(void* const* d_in, const int* in_sizes, int n_in,
                              void* d_out, int out_size) {
    const float* f_t     = (const float*)d_in[0];
    const float* gamma_0 = (const float*)d_in[1];
    const float* gamma_t = (const float*)d_in[2];
    const float* pi_t    = (const float*)d_in[3];
    const float* w_mlp1  = (const float*)d_in[4];
    const float* b_mlp1  = (const float*)d_in[5];
    const float* w_mlp2  = (const float*)d_in[6];
    const float* b_mlp2  = (const float*)d_in[7];
    const float* wq1     = (const float*)d_in[8];
    const float* bq1     = (const float*)d_in[9];
    const float* wk1     = (const float*)d_in[10];
    const float* bk1     = (const float*)d_in[11];
    const float* wv1     = (const float*)d_in[12];
    const float* bv1     = (const float*)d_in[13];
    const float* wq2     = (const float*)d_in[14];
    const float* bq2     = (const float*)d_in[15];
    const float* wk2     = (const float*)d_in[16];
    const float* bk2     = (const float*)d_in[17];
    const float* wv2     = (const float*)d_in[18];
    const float* bv2     = (const float*)d_in[19];
    const float* w_g     = (const float*)d_in[20];
    const float* b_g     = (const float*)d_in[21];
    const float* w_p     = (const float*)d_in[22];
    const float* b_p     = (const float*)d_in[23];
    float* out = (float*)d_out;

    float* base = nullptr;
    cudaGetSymbolAddress((void**)&base, g_scratch);
    float* q   = base;
    float* kv  = q   + HW * 72;
    float* qh1 = kv  + HW * 72;
    float* qh2 = qh1 + HW * 72;
    float* kp  = qh2 + HW * 72;
    float* vp  = kp  + HW * 72;
    float* o1  = vp  + HW * 72;
    float* gp  = o1  + HW * 72;

    const int attn_smem = (36 * KSTR) * 4 + (324 * 18) * 8 + (64 * SSTR + 64) * 4;
    cudaFuncSetAttribute(attn_kernel, cudaFuncAttributeMaxDynamicSharedMemorySize, attn_smem);
    cudaFuncSetAttribute(tc_quad_kernel, cudaFuncAttributeMaxDynamicSharedMemorySize, TCSMEM);
    cudaFuncSetAttribute(tc_pair_kernel, cudaFuncAttributeMaxDynamicSharedMemorySize, TCSMEM);

    mlp_pair_kernel<<<512, 288>>>(gamma_0, gamma_t, pi_t, f_t,
                                  w_mlp1, b_mlp1, w_mlp2, b_mlp2, q, kv);
    tc_quad_kernel<<<1024, 128, TCSMEM>>>(q,  wq1, bq1, qh1,
                                          q,  wq2, bq2, qh2,
                                          kv, wk1, bk1, kp,
                                          kv, wv1, bv1, vp);
    attn_kernel<<<dim3(16, 16), 512, attn_smem>>>(qh1, kp, vp, o1);
    tc_pair_kernel<<<512, 128, TCSMEM>>>(o1, wk2, bk2, kp,
                                         o1, wv2, bv2, vp);
    attn_kernel<<<dim3(16, 16), 512, attn_smem>>>(qh2, kp, vp, gp);
    head_split_kernel<<<64 + (HW * 72 + 255) / 256, 256>>>(gp, w_g, b_g, w_p, b_p, out);
}

// round 15
// speedup vs baseline: 1.0484x; 1.0484x over previous
#include <cuda_runtime.h>
#include <math.h>

#define HW     16384
#define IMG    128
#define TS     8
#define RAD    5
#define KW     11
#define HALO   18
#define NNB    121
#define SSTR   124
#define KSTR   325
#define SCALE  0.11785113019775793f  // 1/sqrt(72)
#define WSZ    5184                  // 72*72
#define WHL    (2 * WSZ)             // hi + lo per matrix

typedef unsigned long long ull;

// 8 x HW x 72 tensors + 6 weight matrices split hi/lo
__device__ float g_scratch[HW * 72 * 8 + 6 * WHL];

__device__ __forceinline__ float gelu_exact(float x) {
    return 0.5f * x * (1.0f + erff(x * 0.70710678118654752f));
}
__device__ __forceinline__ unsigned bf2(float hi, float lo) {
    unsigned r;
    asm("cvt.rn.bf16x2.f32 %0, %1, %2;" : "=r"(r) : "f"(hi), "f"(lo));
    return r;
}
__device__ __forceinline__ float bf_lo(unsigned u) { return __uint_as_float(u << 16); }
__device__ __forceinline__ float bf_hi(unsigned u) { return __uint_as_float(u & 0xffff0000u); }
__device__ __forceinline__ float tf32r(float x) {
    unsigned u;
    asm("cvt.rna.tf32.f32 %0, %1;" : "=r"(u) : "f"(x));
    return __uint_as_float(u);
}

#define MMA_TF32(c0,c1,c2,c3,a0,a1,a2,a3,b0,b1) \
    asm("mma.sync.aligned.m16n8k8.row.col.f32.tf32.tf32.f32 " \
        "{%0,%1,%2,%3},{%4,%5,%6,%7},{%8,%9},{%0,%1,%2,%3};" \
        : "+f"(c0), "+f"(c1), "+f"(c2), "+f"(c3) \
        : "r"(a0), "r"(a1), "r"(a2), "r"(a3), "r"(b0), "r"(b1))

// ---------------------------------------------------------------------------
// prep: split 6 weight matrices into tf32 hi/lo (once per launch)
// ---------------------------------------------------------------------------
__global__ __launch_bounds__(256) void wprep_kernel(const float* __restrict__ W0,
                                                    const float* __restrict__ W1,
                                                    const float* __restrict__ W2,
                                                    const float* __restrict__ W3,
                                                    const float* __restrict__ W4,
                                                    const float* __restrict__ W5,
                                                    float* __restrict__ out) {
    const float* Ws[6] = {W0, W1, W2, W3, W4, W5};
    const float* W = Ws[blockIdx.x];
    float* dst = out + blockIdx.x * WHL;
    for (int i = threadIdx.x; i < WSZ; i += 256) {
        float v = W[i];
        float h = tf32r(v);
        dst[i] = h;
        dst[WSZ + i] = tf32r(v - h);
    }
}

// ---------------------------------------------------------------------------
// Tensor-core GEMM: Y[64px,72] = X[64px,72] @ W + b  (3xTF32)
// 256 threads = 8 warps: warp w -> M-tile (w&3), N-tiles (w>>2 ? 5..8 : 0..4)
// ---------------------------------------------------------------------------
__device__ __forceinline__ void tcproj_body(const float* __restrict__ X,
                                            const float* __restrict__ Whl,
                                            const float* __restrict__ B,
                                            float* __restrict__ Y,
                                            int blk, float* sm) {
    float* Xh = sm;                   // 64*76
    float* Xl = Xh + 64 * 76;         // 64*76
    float* Wh = Xl + 64 * 76;         // 72*72
    float* Wl = Wh + 72 * 72;         // 72*72
    float* bs = Wl + 72 * 72;         // 72
    const int tid = threadIdx.x;
    const int pix0 = blk * 64;

    for (int i = tid; i < 64 * 18; i += 256) {
        int p = i / 18, c4 = i - p * 18;
        float4 v = ((const float4*)(X + pix0 * 72))[i];
        float4 h, l;
        h.x = tf32r(v.x); l.x = tf32r(v.x - h.x);
        h.y = tf32r(v.y); l.y = tf32r(v.y - h.y);
        h.z = tf32r(v.z); l.z = tf32r(v.z - h.z);
        h.w = tf32r(v.w); l.w = tf32r(v.w - h.w);
        *(float4*)&Xh[p * 76 + c4 * 4] = h;
        *(float4*)&Xl[p * 76 + c4 * 4] = l;
    }
    for (int i = tid; i < 72 * 18; i += 256) {
        ((float4*)Wh)[i] = ((const float4*)Whl)[i];
        ((float4*)Wl)[i] = ((const float4*)(Whl + WSZ))[i];
    }
    if (tid < 72) bs[tid] = B[tid];
    __syncthreads();

    const int warp = tid >> 5, lane = tid & 31;
    const int g = lane >> 2, t = lane & 3;
    const int m0 = (warp & 3) * 16;
    const int nh = warp >> 2;
    const int nt0 = nh ? 5 : 0;
    const int ntn = nh ? 4 : 5;

    float c[5][4];
#pragma unroll
    for (int nt = 0; nt < 5; nt++)
#pragma unroll
        for (int j = 0; j < 4; j++) c[nt][j] = 0.0f;

    for (int k0 = 0; k0 < 72; k0 += 8) {
        const int r0 = (m0 + g) * 76 + k0 + t;
        const int r8 = (m0 + g + 8) * 76 + k0 + t;
        unsigned ah0 = __float_as_uint(Xh[r0]);
        unsigned ah1 = __float_as_uint(Xh[r8]);
        unsigned ah2 = __float_as_uint(Xh[r0 + 4]);
        unsigned ah3 = __float_as_uint(Xh[r8 + 4]);
        unsigned al0 = __float_as_uint(Xl[r0]);
        unsigned al1 = __float_as_uint(Xl[r8]);
        unsigned al2 = __float_as_uint(Xl[r0 + 4]);
        unsigned al3 = __float_as_uint(Xl[r8 + 4]);
        const int wr0 = (k0 + t) * 72 + g + nt0 * 8;
        const int wr4 = (k0 + t + 4) * 72 + g + nt0 * 8;
#pragma unroll
        for (int nt = 0; nt < 5; nt++) {
            if (nt >= ntn) break;
            unsigned bh0 = __float_as_uint(Wh[wr0 + nt * 8]);
            unsigned bh1 = __float_as_uint(Wh[wr4 + nt * 8]);
            unsigned bl0 = __float_as_uint(Wl[wr0 + nt * 8]);
            unsigned bl1 = __float_as_uint(Wl[wr4 + nt * 8]);
            MMA_TF32(c[nt][0], c[nt][1], c[nt][2], c[nt][3],
                     ah0, ah1, ah2, ah3, bh0, bh1);
            MMA_TF32(c[nt][0], c[nt][1], c[nt][2], c[nt][3],
                     al0, al1, al2, al3, bh0, bh1);
            MMA_TF32(c[nt][0], c[nt][1], c[nt][2], c[nt][3],
                     ah0, ah1, ah2, ah3, bl0, bl1);
        }
    }

#pragma unroll
    for (int nt = 0; nt < 5; nt++) {
        if (nt >= ntn) break;
        int n = (nt0 + nt) * 8 + 2 * t;
        int row0 = pix0 + m0 + g;
        float b0 = bs[n], b1 = bs[n + 1];
        Y[row0 * 72 + n]           = c[nt][0] + b0;
        Y[row0 * 72 + n + 1]       = c[nt][1] + b1;
        Y[(row0 + 8) * 72 + n]     = c[nt][2] + b0;
        Y[(row0 + 8) * 72 + n + 1] = c[nt][3] + b1;
    }
}

#define TCSMEM ((64 * 76 * 2 + 72 * 72 * 2 + 72) * 4)

__global__ __launch_bounds__(256) void tc_quad_kernel(
        const float* __restrict__ X0, const float* __restrict__ Wa, const float* __restrict__ B0, float* __restrict__ Y0,
        const float* __restrict__ X1, const float* __restrict__ Wb, const float* __restrict__ B1, float* __restrict__ Y1,
        const float* __restrict__ X2, const float* __restrict__ Wc, const float* __restrict__ B2, float* __restrict__ Y2,
        const float* __restrict__ X3, const float* __restrict__ Wd, const float* __restrict__ B3, float* __restrict__ Y3) {
    extern __shared__ float tcs[];
    int gi = blockIdx.x >> 8, blk = blockIdx.x & 255;
    const float *X, *W, *B;
    float* Y;
    if (gi == 0)      { X = X0; W = Wa; B = B0; Y = Y0; }
    else if (gi == 1) { X = X1; W = Wb; B = B1; Y = Y1; }
    else if (gi == 2) { X = X2; W = Wc; B = B2; Y = Y2; }
    else              { X = X3; W = Wd; B = B3; Y = Y3; }
    tcproj_body(X, W, B, Y, blk, tcs);
}

__global__ __launch_bounds__(256) void tc_pair_kernel(
        const float* __restrict__ X0, const float* __restrict__ Wa, const float* __restrict__ B0, float* __restrict__ Y0,
        const float* __restrict__ X1, const float* __restrict__ Wb, const float* __restrict__ B1, float* __restrict__ Y1) {
    extern __shared__ float tcs[];
    int gi = blockIdx.x >> 8, blk = blockIdx.x & 255;
    const float *X, *W, *B;
    float* Y;
    if (gi == 0) { X = X0; W = Wa; B = B0; Y = Y0; }
    else         { X = X1; W = Wb; B = B1; Y = Y1; }
    tcproj_body(X, W, B, Y, blk, tcs);
}

// ---------------------------------------------------------------------------
// MLP (gelu) with fused concat (R7 exact)
// ---------------------------------------------------------------------------
template <int TAIL>
__device__ __forceinline__ void mlp_body(const float* __restrict__ g0,
                                         const float* __restrict__ gt,
                                         const float* __restrict__ tail,
                                         const float* __restrict__ W,
                                         const float* __restrict__ B,
                                         float* __restrict__ Y,
                                         int blk, char* smraw) {
    constexpr int DIN = 64 + TAIL;
    float* Xs = (float*)smraw;        // 64*DIN
    float* Ws = Xs + 64 * DIN;        // DIN*72
    float* bs = Ws + DIN * 72;        // 72
    const int tid = threadIdx.x;
    const int pix0 = blk * 64;

    for (int i = tid; i < 64 * 64; i += 288) {
        int p = i >> 6, c = i & 63;
        Xs[p * DIN + c] = g0[(pix0 + p) * 64 + c] + gt[(pix0 + p) * 64 + c];
    }
    for (int i = tid; i < 64 * TAIL; i += 288) {
        int p = i / TAIL, c = i - p * TAIL;
        Xs[p * DIN + 64 + c] = tail[(pix0 + p) * TAIL + c];
    }
    for (int i = tid; i < DIN * 18; i += 288)
        ((float4*)Ws)[i] = ((const float4*)W)[i];
    if (tid < 72) bs[tid] = B[tid];
    __syncthreads();

    const int og = tid % 18, pg = tid / 18;
    const int ob = og * 4, xb = pg * 4;

    float acc[4][4];
#pragma unroll
    for (int i = 0; i < 4; i++)
#pragma unroll
        for (int j = 0; j < 4; j++) acc[i][j] = 0.0f;

    for (int k = 0; k < DIN; k++) {
        float x0 = Xs[(xb + 0) * DIN + k];
        float x1 = Xs[(xb + 1) * DIN + k];
        float x2 = Xs[(xb + 2) * DIN + k];
        float x3 = Xs[(xb + 3) * DIN + k];
        float4 w = *(const float4*)&Ws[k * 72 + ob];
        acc[0][0] += x0 * w.x; acc[0][1] += x0 * w.y; acc[0][2] += x0 * w.z; acc[0][3] += x0 * w.w;
        acc[1][0] += x1 * w.x; acc[1][1] += x1 * w.y; acc[1][2] += x1 * w.z; acc[1][3] += x1 * w.w;
        acc[2][0] += x2 * w.x; acc[2][1] += x2 * w.y; acc[2][2] += x2 * w.z; acc[2][3] += x2 * w.w;
        acc[3][0] += x3 * w.x; acc[3][1] += x3 * w.y; acc[3][2] += x3 * w.z; acc[3][3] += x3 * w.w;
    }
#pragma unroll
    for (int i = 0; i < 4; i++) {
        float4 r;
        r.x = gelu_exact(acc[i][0] + bs[ob + 0]);
        r.y = gelu_exact(acc[i][1] + bs[ob + 1]);
        r.z = gelu_exact(acc[i][2] + bs[ob + 2]);
        r.w = gelu_exact(acc[i][3] + bs[ob + 3]);
        *(float4*)&Y[(pix0 + xb + i) * 72 + ob] = r;
    }
}

__global__ __launch_bounds__(288) void mlp_pair_kernel(const float* __restrict__ g0,
                                                       const float* __restrict__ gt,
                                                       const float* __restrict__ pi,
                                                       const float* __restrict__ f,
                                                       const float* __restrict__ W1,
                                                       const float* __restrict__ B1,
                                                       const float* __restrict__ W2,
                                                       const float* __restrict__ B2,
                                                       float* __restrict__ Yq,
                                                       float* __restrict__ Ykv) {
    __shared__ char smraw[(64 * 72 + 72 * 72 + 72) * 4];
    if (blockIdx.x < 256) mlp_body<8>(g0, gt, pi, W1, B1, Yq,  blockIdx.x, smraw);
    else                  mlp_body<3>(g0, gt, f,  W2, B2, Ykv, blockIdx.x - 256, smraw);
}

// ---------------------------------------------------------------------------
// Attention (R7 exact, frozen): 8x8 tile, 512 threads.
// ---------------------------------------------------------------------------
__global__ __launch_bounds__(512) void attn_kernel(const float* __restrict__ Q,
                                                   const float* __restrict__ Kp,
                                                   const float* __restrict__ Vp,
                                                   float* __restrict__ O) {
    extern __shared__ char smraw[];
    unsigned* Ksh = (unsigned*)smraw;            // 36 * KSTR  (bf16x2 per entry)
    ull*      Vsh = (ull*)(Ksh + 36 * KSTR);     // 324 * 18   (bf16x4 per entry)
    float*    S   = (float*)(Vsh + 324 * 18);    // 64 * SSTR
    float*    red = S + 64 * SSTR;               // 64

    const int tid = threadIdx.x;
    const int tx = blockIdx.x, ty = blockIdx.y;
    const int ox = tx * TS - RAD, oy = ty * TS - RAD;

    for (int i = tid; i < HALO * HALO * 18; i += 512) {
        int cell = i / 18, j = i - cell * 18;
        int hy = cell / HALO, hx = cell - hy * HALO;
        int gy = oy + hy, gx = ox + hx;
        float4 kv = make_float4(0.f, 0.f, 0.f, 0.f);
        float4 vv = kv;
        if ((unsigned)gy < IMG && (unsigned)gx < IMG) {
            int base = (gy * IMG + gx) * 18;
            kv = __ldg((const float4*)Kp + base + j);
            vv = __ldg((const float4*)Vp + base + j);
        }
        Ksh[(2 * j + 0) * KSTR + cell] = bf2(kv.y, kv.x);
        Ksh[(2 * j + 1) * KSTR + cell] = bf2(kv.w, kv.z);
        unsigned v01 = bf2(vv.y, vv.x);
        unsigned v23 = bf2(vv.w, vv.z);
        Vsh[cell * 18 + j] = ((ull)v23 << 32) | (ull)v01;
    }
    __syncthreads();

    const int p = tid >> 3, sub = tid & 7;
    const int py = p >> 3, px = p & 7;
    const int gy = ty * TS + py, gx = tx * TS + px;

    // ---- phase A: scores ----
    {
        float q[72];
        const float4* qr = (const float4*)(Q + (gy * IMG + gx) * 72);
#pragma unroll
        for (int jj = 0; jj < 18; jj++) {
            float4 t = __ldg(qr + jj);
            q[4 * jj + 0] = t.x; q[4 * jj + 1] = t.y;
            q[4 * jj + 2] = t.z; q[4 * jj + 3] = t.w;
        }
        for (int n = sub; n < NNB; n += 8) {
            int qy = n / 11;
            int qx = n - qy * 11;
            int ny = gy + qy - RAD, nx = gx + qx - RAD;
            float s = -INFINITY;
            if ((unsigned)ny < IMG && (unsigned)nx < IMG) {
                const unsigned* kc = Ksh + (py + qy) * HALO + (px + qx);
                float a0 = 0.f, a1 = 0.f, a2 = 0.f, a3 = 0.f;
#pragma unroll
                for (int j2 = 0; j2 < 36; j2 += 2) {
                    unsigned u0 = kc[(j2 + 0) * KSTR];
                    unsigned u1 = kc[(j2 + 1) * KSTR];
                    a0 = fmaf(q[2 * j2 + 0], bf_lo(u0), a0);
                    a1 = fmaf(q[2 * j2 + 1], bf_hi(u0), a1);
                    a2 = fmaf(q[2 * j2 + 2], bf_lo(u1), a2);
                    a3 = fmaf(q[2 * j2 + 3], bf_hi(u1), a3);
                }
                s = (a0 + a1 + a2 + a3) * SCALE;
            }
            S[p * SSTR + n] = s;
        }
    }
    __syncwarp();

    // ---- softmax: 8-lane cooperative ----
    {
        float* row = S + p * SSTR;
        float m = -INFINITY;
        for (int n = sub; n < NNB; n += 8) m = fmaxf(m, row[n]);
        m = fmaxf(m, __shfl_xor_sync(0xffffffffu, m, 1));
        m = fmaxf(m, __shfl_xor_sync(0xffffffffu, m, 2));
        m = fmaxf(m, __shfl_xor_sync(0xffffffffu, m, 4));
        float sum = 0.f;
        for (int n = sub; n < NNB; n += 8) {
            float e = __expf(row[n] - m);
            row[n] = e;
            sum += e;
        }
        sum += __shfl_xor_sync(0xffffffffu, sum, 1);
        sum += __shfl_xor_sync(0xffffffffu, sum, 2);
        sum += __shfl_xor_sync(0xffffffffu, sum, 4);
        if (sub == 0) red[p] = 1.0f / sum;
    }
    __syncthreads();

    // ---- phase B: attn @ V ----
    for (int u = tid; u < 64 * 18; u += 512) {
        int pp = u / 18, j = u - pp * 18;
        int ppy = pp >> 3, ppx = pp & 7;
        const float* arow = S + pp * SSTR;
        float c0 = 0.f, c1 = 0.f, c2 = 0.f, c3 = 0.f;
#pragma unroll 1
        for (int dy = 0; dy < KW; dy++) {
            const ull* vb = Vsh + (((ppy + dy) * HALO) + ppx) * 18 + j;
            const float* ar = arow + dy * KW;
#pragma unroll
            for (int dx = 0; dx < KW; dx++) {
                float a = ar[dx];
                ull v = vb[dx * 18];
                unsigned u0 = (unsigned)v;
                unsigned u1 = (unsigned)(v >> 32);
                c0 = fmaf(a, bf_lo(u0), c0);
                c1 = fmaf(a, bf_hi(u0), c1);
                c2 = fmaf(a, bf_lo(u1), c2);
                c3 = fmaf(a, bf_hi(u1), c3);
            }
        }
        float r = red[pp];
        float4 res = make_float4(c0 * r, c1 * r, c2 * r, c3 * r);
        int ogy = ty * TS + ppy, ogx = tx * TS + ppx;
        ((float4*)O)[(ogy * IMG + ogx) * 18 + j] = res;
    }
}

// ---------------------------------------------------------------------------
// head (blocks 0..63) + split (blocks 64..)
// ---------------------------------------------------------------------------
__global__ __launch_bounds__(256) void head_split_kernel(const float* __restrict__ gp,
                                                         const float* __restrict__ WG,
                                                         const float* __restrict__ BG,
                                                         const float* __restrict__ WP,
                                                         const float* __restrict__ BP,
                                                         float* __restrict__ out) {
    const int tid = threadIdx.x;
    if (blockIdx.x >= 64) {
        int i = (blockIdx.x - 64) * 256 + tid;
        if (i < HW * 72) {
            int pix = i / 72, c = i - pix * 72;
            float v = gp[i];
            if (c < 64) out[HW * 10 + pix * 64 + c] = v;
            else        out[HW * 74 + pix * 8 + (c - 64)] = v;
        }
        return;
    }
    __shared__ float wg[64 * 7];
    __shared__ float bg[7];
    __shared__ float wp[24];
    __shared__ float bp[3];
    for (int i = tid; i < 448; i += 256) wg[i] = WG[i];
    if (tid < 7)  bg[tid] = BG[tid];
    if (tid < 24) wp[tid] = WP[tid];
    if (tid < 3)  bp[tid] = BP[tid];
    __syncthreads();

    int pix = blockIdx.x * 256 + tid;
    const float* row = gp + pix * 72;

    float gr[7];
#pragma unroll
    for (int j = 0; j < 7; j++) gr[j] = bg[j];
    for (int c = 0; c < 64; c++) {
        float x = row[c];
#pragma unroll
        for (int j = 0; j < 7; j++) gr[j] += x * wg[c * 7 + j];
    }
    float go[7];
#pragma unroll
    for (int j = 0; j < 4; j++) go[j] = 1.0f / (1.0f + __expf(-gr[j]));
    {
        float m = fmaxf(gr[4], fmaxf(gr[5], gr[6]));
        float e0 = __expf(gr[4] - m), e1 = __expf(gr[5] - m), e2 = __expf(gr[6] - m);
        float rs = 1.0f / (e0 + e1 + e2);
        go[4] = e0 * rs; go[5] = e1 * rs; go[6] = e2 * rs;
    }
#pragma unroll
    for (int j = 0; j < 7; j++) out[pix * 7 + j] = go[j];

    float pr[3];
#pragma unroll
    for (int j = 0; j < 3; j++) pr[j] = bp[j];
    for (int c = 0; c < 8; c++) {
        float x = row[64 + c];
#pragma unroll
        for (int j = 0; j < 3; j++) pr[j] += x * wp[c * 3 + j];
    }
    {
        float m = fmaxf(pr[0], fmaxf(pr[1], pr[2]));
        float e0 = __expf(pr[0] - m), e1 = __expf(pr[1] - m), e2 = __expf(pr[2] - m);
        float rs = 1.0f / (e0 + e1 + e2);
        out[HW * 7 + pix * 3 + 0] = e0 * rs;
        out[HW * 7 + pix * 3 + 1] = e1 * rs;
        out[HW * 7 + pix * 3 + 2] = e2 * rs;
    }
}

// ---------------------------------------------------------------------------
extern "C" void kernel_launch(void* const* d_in, const int* in_sizes, int n_in,
                              void* d_out, int out_size) {
    const float* f_t     = (const float*)d_in[0];
    const float* gamma_0 = (const float*)d_in[1];
    const float* gamma_t = (const float*)d_in[2];
    const float* pi_t    = (const float*)d_in[3];
    const float* w_mlp1  = (const float*)d_in[4];
    const float* b_mlp1  = (const float*)d_in[5];
    const float* w_mlp2  = (const float*)d_in[6];
    const float* b_mlp2  = (const float*)d_in[7];
    const float* wq1     = (const float*)d_in[8];
    const float* bq1     = (const float*)d_in[9];
    const float* wk1     = (const float*)d_in[10];
    const float* bk1     = (const float*)d_in[11];
    const float* wv1     = (const float*)d_in[12];
    const float* bv1     = (const float*)d_in[13];
    const float* wq2     = (const float*)d_in[14];
    const float* bq2     = (const float*)d_in[15];
    const float* wk2     = (const float*)d_in[16];
    const float* bk2     = (const float*)d_in[17];
    const float* wv2     = (const float*)d_in[18];
    const float* bv2     = (const float*)d_in[19];
    const float* w_g     = (const float*)d_in[20];
    const float* b_g     = (const float*)d_in[21];
    const float* w_p     = (const float*)d_in[22];
    const float* b_p     = (const float*)d_in[23];
    float* out = (float*)d_out;

    float* base = nullptr;
    cudaGetSymbolAddress((void**)&base, g_scratch);
    float* q   = base;
    float* kv  = q   + HW * 72;
    float* qh1 = kv  + HW * 72;
    float* qh2 = qh1 + HW * 72;
    float* kp  = qh2 + HW * 72;
    float* vp  = kp  + HW * 72;
    float* o1  = vp  + HW * 72;
    float* gp  = o1  + HW * 72;
    float* whl = gp  + HW * 72;   // 6 * WHL
    float* wq1s = whl + 0 * WHL;
    float* wq2s = whl + 1 * WHL;
    float* wk1s = whl + 2 * WHL;
    float* wv1s = whl + 3 * WHL;
    float* wk2s = whl + 4 * WHL;
    float* wv2s = whl + 5 * WHL;

    const int attn_smem = (36 * KSTR) * 4 + (324 * 18) * 8 + (64 * SSTR + 64) * 4;
    cudaFuncSetAttribute(attn_kernel, cudaFuncAttributeMaxDynamicSharedMemorySize, attn_smem);
    cudaFuncSetAttribute(tc_quad_kernel, cudaFuncAttributeMaxDynamicSharedMemorySize, TCSMEM);
    cudaFuncSetAttribute(tc_pair_kernel, cudaFuncAttributeMaxDynamicSharedMemorySize, TCSMEM);

    wprep_kernel<<<6, 256>>>(wq1, wq2, wk1, wv1, wk2, wv2, whl);
    mlp_pair_kernel<<<512, 288>>>(gamma_0, gamma_t, pi_t, f_t,
                                  w_mlp1, b_mlp1, w_mlp2, b_mlp2, q, kv);
    tc_quad_kernel<<<1024, 256, TCSMEM>>>(q,  wq1s, bq1, qh1,
                                          q,  wq2s, bq2, qh2,
                                          kv, wk1s, bk1, kp,
                                          kv, wv1s, bv1, vp);
    attn_kernel<<<dim3(16, 16), 512, attn_smem>>>(qh1, kp, vp, o1);
    tc_pair_kernel<<<512, 256, TCSMEM>>>(o1, wk2s, bk2, kp,
                                         o1, wv2s, bv2, vp);
    attn_kernel<<<dim3(16, 16), 512, attn_smem>>>(qh2, kp, vp, gp);
    head_split_kernel<<<64 + (HW * 72 + 255) / 256, 256>>>(gp, w_g, b_g, w_p, b_p, out);
}